// round 5
// baseline (speedup 1.0000x reference)
#include <cuda_runtime.h>
#include <cuda_fp16.h>
#include <cstdint>

#define VOCAB 100000
#define EMB   128

// Scratch: vocab-major, bias-fused, L2-normalized table in FP16.
// 100000 * 128 * 2B = 25.6 MB — firmly resident in GB300's ~126 MB L2.
__device__ __half g_table[(size_t)VOCAB * EMB];

// ---------------------------------------------------------------------------
// Kernel 1: table[v][:] = (half) normalize(W[:, v] + b)
// One block per 32 vocab entries. Block = 256 threads.
// Fires griddepcontrol.launch_dependents after its stores are issued, so the
// PDL-launched gather kernel can start its prologue early.
// ---------------------------------------------------------------------------
__global__ __launch_bounds__(256) void build_table_kernel(
        const float* __restrict__ W,
        const float* __restrict__ b) {
    __shared__ float tile[EMB][33];   // [j][v_local], pad -> conflict-free reduce

    const int v0   = blockIdx.x * 32;
    const int tid  = threadIdx.x;
    const int lane = tid & 31;
    const int wid  = tid >> 5;        // 0..7

    // Load + bias: warp reads one j-row of 32 consecutive vocab cols (128B line).
    #pragma unroll
    for (int k = 0; k < 16; k++) {
        int j = k * 8 + wid;
        tile[j][lane] = W[(size_t)j * VOCAB + v0 + lane] + b[j];
    }
    __syncthreads();

    // Each warp normalizes 4 vocab rows and writes them as half2.
    #pragma unroll
    for (int r = 0; r < 4; r++) {
        const int v = wid * 4 + r;

        float s = 0.f;
        #pragma unroll
        for (int k = 0; k < 4; k++) {
            float e = tile[lane + 32 * k][v];
            s += e * e;
        }
        #pragma unroll
        for (int o = 16; o > 0; o >>= 1)
            s += __shfl_xor_sync(0xFFFFFFFFu, s, o);

        const float inv = 1.0f / fmaxf(sqrtf(s), 1e-12f);

        __half2* dst = reinterpret_cast<__half2*>(g_table + (size_t)(v0 + v) * EMB);
        dst[lane]      = __floats2half2_rn(tile[2 * lane][v] * inv,
                                           tile[2 * lane + 1][v] * inv);
        dst[lane + 32] = __floats2half2_rn(tile[64 + 2 * lane][v] * inv,
                                           tile[64 + 2 * lane + 1][v] * inv);
    }

    // Signal dependent (gather) launch readiness from this block.
    asm volatile("griddepcontrol.launch_dependents;" ::: "memory");
}

// ---------------------------------------------------------------------------
// Kernel 2 (PDL secondary): gather-copy + fp16->fp32 widen.
// Prologue (index loads) runs BEFORE griddepcontrol.wait so it overlaps the
// build kernel's tail. Warp handles TOK_PER_WARP tokens; lane l moves 4
// halves (256B coalesced read / 512B coalesced write per token). Output
// stores use evict-first (.cs) so the stream doesn't evict the table from L2.
// ---------------------------------------------------------------------------
#define TOK_PER_WARP 8

__global__ __launch_bounds__(256) void gather_kernel(
        const int* __restrict__ x,
        float* __restrict__ out,
        int n_tok) {
    const int gwarp = (blockIdx.x * blockDim.x + threadIdx.x) >> 5;
    const int lane  = threadIdx.x & 31;
    const int t0    = gwarp * TOK_PER_WARP;

    if (t0 + TOK_PER_WARP <= n_tok) {
        // ---- prologue: independent of the table — overlaps build tail ----
        int idx[TOK_PER_WARP];
        #pragma unroll
        for (int r = 0; r < TOK_PER_WARP; r++)
            idx[r] = __ldg(&x[t0 + r]);

        // ---- wait for build completion before touching g_table ----
        asm volatile("griddepcontrol.wait;" ::: "memory");

        uint2 h[TOK_PER_WARP];
        #pragma unroll
        for (int r = 0; r < TOK_PER_WARP; r++)
            h[r] = __ldg(reinterpret_cast<const uint2*>(
                       g_table + (size_t)idx[r] * EMB) + lane);

        #pragma unroll
        for (int r = 0; r < TOK_PER_WARP; r++) {
            float2 f0 = __half22float2(*reinterpret_cast<__half2*>(&h[r].x));
            float2 f1 = __half22float2(*reinterpret_cast<__half2*>(&h[r].y));
            float4 o;
            o.x = f0.x; o.y = f0.y; o.z = f1.x; o.w = f1.y;
            __stcs(reinterpret_cast<float4*>(out + (size_t)(t0 + r) * EMB) + lane, o);
        }
    } else if (t0 < n_tok) {
        asm volatile("griddepcontrol.wait;" ::: "memory");
        for (int t = t0; t < n_tok; t++) {
            uint2 h = __ldg(reinterpret_cast<const uint2*>(
                          g_table + (size_t)__ldg(&x[t]) * EMB) + lane);
            float2 f0 = __half22float2(*reinterpret_cast<__half2*>(&h.x));
            float2 f1 = __half22float2(*reinterpret_cast<__half2*>(&h.y));
            float4 o;
            o.x = f0.x; o.y = f0.y; o.z = f1.x; o.w = f1.y;
            __stcs(reinterpret_cast<float4*>(out + (size_t)t * EMB) + lane, o);
        }
    }
    // Warps entirely past the tail touch nothing — safe to exit without waiting.
}

// ---------------------------------------------------------------------------
extern "C" void kernel_launch(void* const* d_in, const int* in_sizes, int n_in,
                              void* d_out, int out_size) {
    const int*   x = (const int*)d_in[0];    // [4096, 200] int32
    const float* W = (const float*)d_in[1];  // [128, 100000] fp32
    const float* b = (const float*)d_in[2];  // [128] fp32
    float* out = (float*)d_out;              // [4096, 200, 128] fp32

    const int n_tok = in_sizes[0];           // 819200

    build_table_kernel<<<VOCAB / 32, 256>>>(W, b);

    const int warps_needed = (n_tok + TOK_PER_WARP - 1) / TOK_PER_WARP;
    const int blocks = (warps_needed + 7) / 8;   // 8 warps per 256-thread block

    // Launch gather as a PDL secondary: it may begin (prologue) before
    // build_table_kernel fully completes; griddepcontrol.wait provides the
    // data dependency.
    cudaLaunchConfig_t cfg = {};
    cfg.gridDim  = dim3(blocks, 1, 1);
    cfg.blockDim = dim3(256, 1, 1);
    cfg.dynamicSmemBytes = 0;
    cfg.stream = 0;
    cudaLaunchAttribute attr[1];
    attr[0].id = cudaLaunchAttributeProgrammaticStreamSerialization;
    attr[0].val.programmaticStreamSerializationAllowed = 1;
    cfg.attrs = attr;
    cfg.numAttrs = 1;
    cudaLaunchKernelEx(&cfg, gather_kernel, x, out, n_tok);
}